// round 1
// baseline (speedup 1.0000x reference)
#include <cuda_runtime.h>
#include <math_constants.h>

#define NB 50          // NB_STEPS
#define S51 51         // NB+1 quadrature points
#define BATCH 4096
#define NFEAT 100
#define ALPHA_INV (1.0f/0.9f)

// ---------------- device globals (scratch; no allocations allowed) ----------
__device__ float g_xm[BATCH];
__device__ float g_x[BATCH];
__device__ float g_x2[BATCH];
__device__ float g_xfinal;
__device__ float g_ccw[S51];
__device__ float g_ccs[S51];

// ---------------- CC weights (computed in fp64 on device, every launch) -----
__global__ void k_init_cc() {
    int j = threadIdx.x;
    if (j > NB) return;
    double s = 0.0;
    for (int i = 0; i <= NB; ++i) {
        double w;
        if (i & 1)        w = 0.0;
        else if (i == 0)  w = 1.0;
        else              w = 2.0 / (1.0 - (double)i * (double)i);
        double l;
        if (j == 0) {
            l = 0.5;
        } else {
            l = cos((double)i * (double)j * CUDART_PI / (double)NB);
            if (j == NB) l *= 0.5;
        }
        l *= 2.0 / (double)NB;
        s += l * w;
    }
    g_ccw[j] = (float)s;
    g_ccs[j] = (float)cos((double)j * CUDART_PI / (double)NB);
}

// ---------------- xm = x_ @ log_weight (warp per row) ------------------------
__global__ void k_xm(const float* __restrict__ x_, const float* __restrict__ lw) {
    int warp = (blockIdx.x * blockDim.x + threadIdx.x) >> 5;
    int lane = threadIdx.x & 31;
    if (warp >= BATCH) return;
    const float* row = x_ + (size_t)warp * NFEAT;
    float p = 0.f;
    for (int j = lane; j < NFEAT; j += 32) p = fmaf(row[j], lw[j], p);
    #pragma unroll
    for (int off = 16; off; off >>= 1) p += __shfl_xor_sync(0xffffffffu, p, off);
    if (lane == 0) g_xm[warp] = p;
}

// ---------------- per-step prep: x, x2, global max(x2)+10 --------------------
__global__ void k_prep(const float* __restrict__ sp, const float* __restrict__ out, int step) {
    __shared__ float smax[1024];
    int tid = threadIdx.x;
    float lam = 1.f / (1.f + __expf(-sp[0]));
    float lmax = -CUDART_INF_F;
    for (int b = tid; b < BATCH; b += 1024) {
        float I1v = step ? out[b]             : 0.f;
        float I2v = step ? out[2 * BATCH + b] : 0.f;
        float xmv = g_xm[b];
        float xv  = (1.f - lam) * xmv + lam * I1v;
        float x2v = (1.f - lam) * xmv + lam * I2v;
        g_x[b]  = xv;
        g_x2[b] = x2v;
        lmax = fmaxf(lmax, x2v);
    }
    smax[tid] = lmax;
    __syncthreads();
    for (int off = 512; off; off >>= 1) {
        if (tid < off) smax[tid] = fmaxf(smax[tid], smax[tid + off]);
        __syncthreads();
    }
    if (tid == 0) g_xfinal = smax[0] + 10.f;
}

// ---------------- fused integrand + quadrature kernel ------------------------
// MODE 0: f1, integrate 0..x[b]  (+ out_first at slot s==51, evaluated at x2[b])
// MODE 1: f2, integrate x2[b]..xfinal, scaled by 1/ALPHA
// Block: 256 threads = 4 batch rows x 64 slots (51 quad samples active).
template <int MODE>
__global__ void __launch_bounds__(256, 1) k_integral(
    const float* __restrict__ W0, const float* __restrict__ b0,
    const float* __restrict__ W1, const float* __restrict__ b1,
    const float* __restrict__ W2, const float* __restrict__ b2,
    const float* __restrict__ W3, const float* __restrict__ b3,
    const float* __restrict__ Wf, const float* __restrict__ h,
    float* __restrict__ out)
{
    __shared__ __align__(16) float sW1[64 * 64];
    __shared__ __align__(16) float sW2[64 * 64];
    __shared__ __align__(16) float sw0x[64];
    __shared__ __align__(16) float sb1[64];
    __shared__ __align__(16) float sb2[64];
    __shared__ __align__(16) float sW3[64];
    __shared__ float shp[4][64];
    __shared__ float sWf[5];
    __shared__ float sb3v;
    __shared__ float sred[8];

    const int tid = threadIdx.x;
    for (int i = tid; i < 64 * 64; i += 256) { sW1[i] = W1[i]; sW2[i] = W2[i]; }
    if (tid < 64) {
        sw0x[tid] = W0[tid * 5];
        sb1[tid]  = b1[tid];
        sb2[tid]  = b2[tid];
        sW3[tid]  = W3[tid];
    }
    if (tid < 5)   sWf[tid] = Wf[tid];
    if (tid == 255) sb3v = b3[0];

    const int bl = tid >> 6;        // batch row within block (0..3)
    const int s  = tid & 63;        // quadrature slot (0..63, 51 active)
    const int b  = (blockIdx.x << 2) + bl;

    {   // hpart[j] = b0[j] + W0[j,1:5] . h[b]   (thread -> neuron s of row bl)
        float hp = b0[s];
        #pragma unroll
        for (int d = 0; d < 4; ++d) hp = fmaf(W0[s * 5 + 1 + d], h[b * 4 + d], hp);
        shp[bl][s] = hp;
    }
    __syncthreads();

    float lo, hi;
    if (MODE == 0) { lo = 0.f;      hi = g_x[b];   }
    else           { lo = g_x2[b];  hi = g_xfinal; }

    const int sc = (s < S51) ? s : 0;
    float X = lo + (hi - lo) * (g_ccs[sc] + 1.f) * 0.5f;
    if (MODE == 0 && s == S51) X = g_x2[b];   // out_first evaluation point

    // ---- MLP: 5 -> 64 -> 64 -> 64 -> 1, relu x3, elu head ----
    const float* hpb = shp[bl];
    float a[64];
    #pragma unroll
    for (int j = 0; j < 64; ++j) a[j] = fmaxf(fmaf(sw0x[j], X, hpb[j]), 0.f);

    float c[64];
    #pragma unroll
    for (int j = 0; j < 64; ++j) {
        float acc = sb1[j];
        const float4* w = (const float4*)(sW1 + j * 64);
        #pragma unroll
        for (int k = 0; k < 16; ++k) {
            float4 v = w[k];
            acc = fmaf(v.x, a[4 * k + 0], acc);
            acc = fmaf(v.y, a[4 * k + 1], acc);
            acc = fmaf(v.z, a[4 * k + 2], acc);
            acc = fmaf(v.w, a[4 * k + 3], acc);
        }
        c[j] = fmaxf(acc, 0.f);
    }
    #pragma unroll
    for (int j = 0; j < 64; ++j) {
        float acc = sb2[j];
        const float4* w = (const float4*)(sW2 + j * 64);
        #pragma unroll
        for (int k = 0; k < 16; ++k) {
            float4 v = w[k];
            acc = fmaf(v.x, c[4 * k + 0], acc);
            acc = fmaf(v.y, c[4 * k + 1], acc);
            acc = fmaf(v.z, c[4 * k + 2], acc);
            acc = fmaf(v.w, c[4 * k + 3], acc);
        }
        a[j] = fmaxf(acc, 0.f);
    }
    float y = sb3v;
    #pragma unroll
    for (int k = 0; k < 64; ++k) y = fmaf(sW3[k], a[k], y);

    // z = elu(y) + 1 >= 0
    float z  = (y > 0.f) ? (y + 1.f) : __expf(y);
    float lg = __log2f(z);

    const float P0 = (MODE == 0) ? 1.1f : 1.5f;
    const float P1 = (MODE == 0) ? 1.1f : 2.0f;
    const float P2 = (MODE == 0) ? 1.5f : 2.5f;
    const float P3 = (MODE == 0) ? 2.0f : 3.0f;
    const float P4 = (MODE == 0) ? 2.5f : 3.5f;

    float g = 0.f;
    g += __fdividef(sWf[0], exp2f(P0 * lg) + 1.f);
    g += __fdividef(sWf[1], exp2f(P1 * lg) + 1.f);
    g += __fdividef(sWf[2], exp2f(P2 * lg) + 1.f);
    g += __fdividef(sWf[3], exp2f(P3 * lg) + 1.f);
    g += __fdividef(sWf[4], exp2f(P4 * lg) + 1.f);
    float val = fmaxf(g, 0.f);

    if (MODE == 0 && s == S51) out[BATCH + b] = val;   // out_first

    float contrib = (s < S51) ? g_ccw[s] * val : 0.f;
    #pragma unroll
    for (int off = 16; off; off >>= 1)
        contrib += __shfl_xor_sync(0xffffffffu, contrib, off);
    if ((tid & 31) == 0) sred[tid >> 5] = contrib;
    __syncthreads();
    if (s == 0) {
        float ssum = sred[bl * 2] + sred[bl * 2 + 1];
        if (MODE == 0) out[b]             = ssum * hi * 0.5f;                       // I1
        else           out[2 * BATCH + b] = ssum * (hi - lo) * 0.5f * ALPHA_INV;    // I2
    }
}

// ---------------- launch ------------------------------------------------------
extern "C" void kernel_launch(void* const* d_in, const int* in_sizes, int n_in,
                              void* d_out, int out_size) {
    (void)in_sizes; (void)n_in; (void)out_size;
    const float* x_  = (const float*)d_in[0];
    const float* h_  = (const float*)d_in[1];
    const float* lw  = (const float*)d_in[2];
    const float* sp  = (const float*)d_in[3];
    const float* f1p[9] = { (const float*)d_in[4],  (const float*)d_in[5],
                            (const float*)d_in[6],  (const float*)d_in[7],
                            (const float*)d_in[8],  (const float*)d_in[9],
                            (const float*)d_in[10], (const float*)d_in[11],
                            (const float*)d_in[12] };
    const float* f2p[9] = { (const float*)d_in[13], (const float*)d_in[14],
                            (const float*)d_in[15], (const float*)d_in[16],
                            (const float*)d_in[17], (const float*)d_in[18],
                            (const float*)d_in[19], (const float*)d_in[20],
                            (const float*)d_in[21] };
    float* out = (float*)d_out;

    k_init_cc<<<1, 64>>>();
    k_xm<<<BATCH / 8, 256>>>(x_, lw);   // 8 warps/block, warp per row

    for (int step = 0; step < 2; ++step) {
        k_prep<<<1, 1024>>>(sp, out, step);
        k_integral<0><<<BATCH / 4, 256>>>(f1p[0], f1p[1], f1p[2], f1p[3],
                                          f1p[4], f1p[5], f1p[6], f1p[7],
                                          f1p[8], h_, out);
        k_integral<1><<<BATCH / 4, 256>>>(f2p[0], f2p[1], f2p[2], f2p[3],
                                          f2p[4], f2p[5], f2p[6], f2p[7],
                                          f2p[8], h_, out);
    }
}

// round 2
// speedup vs baseline: 1.7036x; 1.7036x over previous
#include <cuda_runtime.h>
#include <math_constants.h>

#define NB 50          // NB_STEPS
#define S51 51         // NB+1 quadrature points
#define BATCH 4096
#define NFEAT 100
#define ALPHA_INV (1.0f/0.9f)
#define WSTRIDE 68     // padded shared row stride (floats): 272B, 16B-aligned, 4-way store conflict only

// ---------------- device globals (scratch; no allocations allowed) ----------
__device__ float g_xm[BATCH];
__device__ float g_x[BATCH];
__device__ float g_x2[BATCH];
__device__ float g_xfinal;
__device__ float g_ccw[S51];
__device__ float g_ccs[S51];
__device__ float g_vals[BATCH * 52];

// ---------------- packed f32x2 helpers (FFMA2 only reachable via PTX) -------
__device__ __forceinline__ unsigned long long fma2(unsigned long long a,
                                                   unsigned long long b,
                                                   unsigned long long c) {
    unsigned long long d;
    asm("fma.rn.f32x2 %0, %1, %2, %3;" : "=l"(d) : "l"(a), "l"(b), "l"(c));
    return d;
}
__device__ __forceinline__ unsigned long long pack2(float lo, float hi) {
    unsigned long long d;
    asm("mov.b64 %0, {%1, %2};" : "=l"(d) : "f"(lo), "f"(hi));
    return d;
}
__device__ __forceinline__ void unpack2(unsigned long long v, float& lo, float& hi) {
    asm("mov.b64 {%0, %1}, %2;" : "=f"(lo), "=f"(hi) : "l"(v));
}

// 64->64 dense layer + ReLU, weights pre-transposed in shared: sWp[k*WSTRIDE + j] = W[j][k].
// Accumulators packed over neuron pairs; activations in/out through a[64] (in regs).
__device__ __forceinline__ void layer64(const float* __restrict__ sWp,
                                        const float* __restrict__ sbias,
                                        float* a) {
    unsigned long long acc[32];
    #pragma unroll
    for (int jp = 0; jp < 32; ++jp) acc[jp] = pack2(sbias[2 * jp], sbias[2 * jp + 1]);

    #pragma unroll 4
    for (int k = 0; k < 64; ++k) {
        unsigned long long a2 = pack2(a[k], a[k]);
        const ulonglong2* w = (const ulonglong2*)(sWp + k * WSTRIDE);
        #pragma unroll
        for (int q = 0; q < 16; ++q) {
            ulonglong2 wv = w[q];                 // uniform address -> broadcast LDS.128
            acc[2 * q]     = fma2(wv.x, a2, acc[2 * q]);
            acc[2 * q + 1] = fma2(wv.y, a2, acc[2 * q + 1]);
        }
    }
    #pragma unroll
    for (int jp = 0; jp < 32; ++jp) {
        float lo, hi;
        unpack2(acc[jp], lo, hi);
        a[2 * jp]     = fmaxf(lo, 0.f);
        a[2 * jp + 1] = fmaxf(hi, 0.f);
    }
}

// ---------------- CC weights (fp64 on device, every launch) -----------------
__global__ void k_init_cc() {
    int j = threadIdx.x;
    if (j > NB) return;
    double s = 0.0;
    for (int i = 0; i <= NB; ++i) {
        double w;
        if (i & 1)        w = 0.0;
        else if (i == 0)  w = 1.0;
        else              w = 2.0 / (1.0 - (double)i * (double)i);
        double l;
        if (j == 0) {
            l = 0.5;
        } else {
            l = cos((double)i * (double)j * CUDART_PI / (double)NB);
            if (j == NB) l *= 0.5;
        }
        l *= 2.0 / (double)NB;
        s += l * w;
    }
    g_ccw[j] = (float)s;
    g_ccs[j] = (float)cos((double)j * CUDART_PI / (double)NB);
}

// ---------------- xm = x_ @ log_weight (warp per row) ------------------------
__global__ void k_xm(const float* __restrict__ x_, const float* __restrict__ lw) {
    int warp = (blockIdx.x * blockDim.x + threadIdx.x) >> 5;
    int lane = threadIdx.x & 31;
    if (warp >= BATCH) return;
    const float* row = x_ + (size_t)warp * NFEAT;
    float p = 0.f;
    for (int j = lane; j < NFEAT; j += 32) p = fmaf(row[j], lw[j], p);
    #pragma unroll
    for (int off = 16; off; off >>= 1) p += __shfl_xor_sync(0xffffffffu, p, off);
    if (lane == 0) g_xm[warp] = p;
}

// ---------------- per-step prep: x, x2, global max(x2)+10 --------------------
__global__ void k_prep(const float* __restrict__ sp, const float* __restrict__ out, int step) {
    __shared__ float smax[1024];
    int tid = threadIdx.x;
    float lam = 1.f / (1.f + __expf(-sp[0]));
    float lmax = -CUDART_INF_F;
    for (int b = tid; b < BATCH; b += 1024) {
        float I1v = step ? out[b]             : 0.f;
        float I2v = step ? out[2 * BATCH + b] : 0.f;
        float xmv = g_xm[b];
        float xv  = (1.f - lam) * xmv + lam * I1v;
        float x2v = (1.f - lam) * xmv + lam * I2v;
        g_x[b]  = xv;
        g_x2[b] = x2v;
        lmax = fmaxf(lmax, x2v);
    }
    smax[tid] = lmax;
    __syncthreads();
    for (int off = 512; off; off >>= 1) {
        if (tid < off) smax[tid] = fmaxf(smax[tid], smax[tid + off]);
        __syncthreads();
    }
    if (tid == 0) g_xfinal = smax[0] + 10.f;
}

// ---------------- flat integrand eval kernel ---------------------------------
// One thread per (row, slot) evaluation. MODE 0: f1, 52 slots/row (51 quad + 1
// out_first at x2). MODE 1: f2, 51 slots/row. Quad contributions prescaled by
// ccw into g_vals; a separate reduce kernel sums deterministically.
template <int MODE>
__global__ void __launch_bounds__(256, 1) k_eval(
    const float* __restrict__ W0, const float* __restrict__ b0,
    const float* __restrict__ W1, const float* __restrict__ b1,
    const float* __restrict__ W2, const float* __restrict__ b2,
    const float* __restrict__ W3, const float* __restrict__ b3,
    const float* __restrict__ Wf, const float* __restrict__ h,
    float* __restrict__ out)
{
    __shared__ __align__(16) float sW0[64 * 8];           // [j][0..4]=W0 row, [5]=b0
    __shared__ __align__(16) float sWp1[64 * WSTRIDE];    // transposed W1
    __shared__ __align__(16) float sWp2[64 * WSTRIDE];    // transposed W2
    __shared__ __align__(16) float sb1[64];
    __shared__ __align__(16) float sb2[64];
    __shared__ __align__(16) float sW3[64];
    __shared__ float sWf[5];
    __shared__ float sb3;

    const int tid = threadIdx.x;

    for (int i = tid; i < 4096; i += 256) {
        int j = i >> 6, k = i & 63;
        sWp1[k * WSTRIDE + j] = W1[i];
        sWp2[k * WSTRIDE + j] = W2[i];
    }
    if (tid < 64) {
        #pragma unroll
        for (int d = 0; d < 5; ++d) sW0[tid * 8 + d] = W0[tid * 5 + d];
        sW0[tid * 8 + 5] = b0[tid];
        sb1[tid] = b1[tid];
        sb2[tid] = b2[tid];
        sW3[tid] = W3[tid];
    }
    if (tid < 5)    sWf[tid] = Wf[tid];
    if (tid == 255) sb3 = b3[0];

    const int NS   = (MODE == 0) ? 52 : 51;
    const int e    = blockIdx.x * 256 + tid;     // grids sized exactly, no bounds check
    const int row  = e / NS;
    const int slot = e - row * NS;

    float lo, hi;
    if (MODE == 0) { lo = 0.f;       hi = g_x[row];  }
    else           { lo = g_x2[row]; hi = g_xfinal;  }
    const int sc = (slot < S51) ? slot : 0;
    float X = lo + (hi - lo) * (g_ccs[sc] + 1.f) * 0.5f;
    if (MODE == 0 && slot == S51) X = g_x2[row];   // out_first evaluation point

    const float h0 = h[row * 4 + 0], h1 = h[row * 4 + 1];
    const float h2 = h[row * 4 + 2], h3 = h[row * 4 + 3];
    const float ccwv = g_ccw[sc];

    __syncthreads();

    // ---- layer 0: 5 -> 64 + ReLU ----
    float a[64];
    #pragma unroll
    for (int j = 0; j < 64; ++j) {
        const float* w = sW0 + j * 8;
        float acc = w[5];
        acc = fmaf(w[0], X,  acc);
        acc = fmaf(w[1], h0, acc);
        acc = fmaf(w[2], h1, acc);
        acc = fmaf(w[3], h2, acc);
        acc = fmaf(w[4], h3, acc);
        a[j] = fmaxf(acc, 0.f);
    }

    // ---- layers 1,2: 64 -> 64 + ReLU (packed FFMA2) ----
    layer64(sWp1, sb1, a);
    layer64(sWp2, sb2, a);

    // ---- layer 3: 64 -> 1 ----
    float y = sb3;
    #pragma unroll
    for (int k = 0; k < 64; ++k) y = fmaf(sW3[k], a[k], y);

    // ---- ELU + 1, power features, final relu ----
    float z  = (y > 0.f) ? (y + 1.f) : __expf(y);
    float lg = __log2f(z);

    const float P0 = (MODE == 0) ? 1.1f : 1.5f;
    const float P1 = (MODE == 0) ? 1.1f : 2.0f;
    const float P2 = (MODE == 0) ? 1.5f : 2.5f;
    const float P3 = (MODE == 0) ? 2.0f : 3.0f;
    const float P4 = (MODE == 0) ? 2.5f : 3.5f;

    float g = 0.f;
    g += __fdividef(sWf[0], exp2f(P0 * lg) + 1.f);
    g += __fdividef(sWf[1], exp2f(P1 * lg) + 1.f);
    g += __fdividef(sWf[2], exp2f(P2 * lg) + 1.f);
    g += __fdividef(sWf[3], exp2f(P3 * lg) + 1.f);
    g += __fdividef(sWf[4], exp2f(P4 * lg) + 1.f);
    float val = fmaxf(g, 0.f);

    if (MODE == 0 && slot == S51) {
        out[BATCH + row] = val;                  // out_first
    } else {
        g_vals[row * 52 + slot] = ccwv * val;    // prescaled quad contribution
    }
}

// ---------------- deterministic quadrature reduce -----------------------------
template <int MODE>
__global__ void k_reduce(float* __restrict__ out) {
    int row  = blockIdx.x * 8 + (threadIdx.x >> 5);
    int lane = threadIdx.x & 31;
    const float* v = g_vals + row * 52;
    float s = v[lane];
    if (lane < 19) s += v[32 + lane];            // 51 = 32 + 19
    #pragma unroll
    for (int off = 16; off; off >>= 1) s += __shfl_xor_sync(0xffffffffu, s, off);
    if (lane == 0) {
        if (MODE == 0) out[row]             = s * g_x[row] * 0.5f;
        else           out[2 * BATCH + row] = s * (g_xfinal - g_x2[row]) * 0.5f * ALPHA_INV;
    }
}

// ---------------- launch ------------------------------------------------------
extern "C" void kernel_launch(void* const* d_in, const int* in_sizes, int n_in,
                              void* d_out, int out_size) {
    (void)in_sizes; (void)n_in; (void)out_size;
    const float* x_ = (const float*)d_in[0];
    const float* h_ = (const float*)d_in[1];
    const float* lw = (const float*)d_in[2];
    const float* sp = (const float*)d_in[3];
    const float* f1p[9] = { (const float*)d_in[4],  (const float*)d_in[5],
                            (const float*)d_in[6],  (const float*)d_in[7],
                            (const float*)d_in[8],  (const float*)d_in[9],
                            (const float*)d_in[10], (const float*)d_in[11],
                            (const float*)d_in[12] };
    const float* f2p[9] = { (const float*)d_in[13], (const float*)d_in[14],
                            (const float*)d_in[15], (const float*)d_in[16],
                            (const float*)d_in[17], (const float*)d_in[18],
                            (const float*)d_in[19], (const float*)d_in[20],
                            (const float*)d_in[21] };
    float* out = (float*)d_out;

    k_init_cc<<<1, 64>>>();
    k_xm<<<BATCH / 8, 256>>>(x_, lw);

    for (int step = 0; step < 2; ++step) {
        k_prep<<<1, 1024>>>(sp, out, step);
        // MODE 0: 4096*52 = 212992 evals = 832 blocks * 256
        k_eval<0><<<832, 256>>>(f1p[0], f1p[1], f1p[2], f1p[3], f1p[4],
                                f1p[5], f1p[6], f1p[7], f1p[8], h_, out);
        k_reduce<0><<<BATCH / 8, 256>>>(out);
        // MODE 1: 4096*51 = 208896 evals = 816 blocks * 256
        k_eval<1><<<816, 256>>>(f2p[0], f2p[1], f2p[2], f2p[3], f2p[4],
                                f2p[5], f2p[6], f2p[7], f2p[8], h_, out);
        k_reduce<1><<<BATCH / 8, 256>>>(out);
    }
}